// round 13
// baseline (speedup 1.0000x reference)
#include <cuda_runtime.h>
#include <cuda_fp16.h>
#include <math_constants.h>
#include <cstdint>

#define MAXN 131072
#define MAXB 32
#define EPSV 1e-5f

// ---------------- scratch (static device globals; no allocation) ----------------
__device__ __align__(16) __half g_y2h [512 * MAXN];   // y2 partial (no ysym) fp16 [c][N]
__device__ __align__(16) __half g_W2a_h[512 * 512];
__device__ __align__(16) __half g_W2b_h[1024 * 512];
__device__ __align__(16) __half g_W1b_h[256 * 128];
__device__ float    g_psum[512 * 2048];   // per-(c, block, half) partial sums
__device__ float    g_psq [512 * 2048];
__device__ float    g_xpart[128 * 9];
__device__ float    g_Wf1[128 * 3];
__device__ float    g_bf1[128];
__device__ float    g_a2[512];
__device__ float    g_c2[512];
__device__ unsigned g_pool1u[MAXB * 256];
__device__ float    g_pool1f[MAXB * 256];
__device__ float    g_ysym[MAXB * 512];    // [seg][c] fp32 sym contribution
__device__ unsigned g_pool2u[MAXB * 1024];
__device__ int      g_off[MAXB + 1];
__device__ __align__(8) unsigned char g_segid[MAXN];

// monotonic float<->uint key for exact atomic max
__device__ __forceinline__ unsigned fkey(float f) {
    unsigned u = __float_as_uint(f);
    return (u & 0x80000000u) ? ~u : (u | 0x80000000u);
}
__device__ __forceinline__ float funkey(unsigned k) {
    return (k & 0x80000000u) ? __uint_as_float(k & 0x7fffffffu)
                             : __uint_as_float(~k);
}

// ---------------- PTX helpers ----------------
__device__ __forceinline__ unsigned smem_u32(const void* p) {
    return (unsigned)__cvta_generic_to_shared(p);
}
__device__ __forceinline__ void cp16(unsigned dst, const void* src) {
    asm volatile("cp.async.cg.shared.global [%0], [%1], 16;\n" :: "r"(dst), "l"(src));
}
__device__ __forceinline__ void cp_commit() { asm volatile("cp.async.commit_group;\n" ::); }
__device__ __forceinline__ void cp_wait0()  { asm volatile("cp.async.wait_group 0;\n" ::); }
__device__ __forceinline__ void cp_wait2()  { asm volatile("cp.async.wait_group 2;\n" ::); }
__device__ __forceinline__ void ldsm_x4(unsigned* r, unsigned addr) {
    asm volatile("ldmatrix.sync.aligned.m8n8.x4.shared.b16 {%0,%1,%2,%3},[%4];"
                 : "=r"(r[0]), "=r"(r[1]), "=r"(r[2]), "=r"(r[3]) : "r"(addr));
}
__device__ __forceinline__ void ldsm_x4_t(unsigned* r, unsigned addr) {
    asm volatile("ldmatrix.sync.aligned.m8n8.x4.trans.shared.b16 {%0,%1,%2,%3},[%4];"
                 : "=r"(r[0]), "=r"(r[1]), "=r"(r[2]), "=r"(r[3]) : "r"(addr));
}
__device__ __forceinline__ void mma16816(float* d, const unsigned* a, unsigned b0, unsigned b1) {
    asm volatile("mma.sync.aligned.m16n8k16.row.col.f32.f16.f16.f32 "
                 "{%0,%1,%2,%3},{%4,%5,%6,%7},{%8,%9},{%0,%1,%2,%3};"
                 : "+f"(d[0]), "+f"(d[1]), "+f"(d[2]), "+f"(d[3])
                 : "r"(a[0]), "r"(a[1]), "r"(a[2]), "r"(a[3]), "r"(b0), "r"(b1));
}

// ---------------- K0: offsets + pool init ----------------
__global__ void k_init(const int* npts, int B) {
    int tid = blockIdx.x * blockDim.x + threadIdx.x;
    if (blockIdx.x == 0 && threadIdx.x == 0) {
        int acc = 0; g_off[0] = 0;
        for (int b = 0; b < B; b++) { acc += npts[b]; g_off[b + 1] = acc; }
    }
    int stride = gridDim.x * blockDim.x;
    for (int i = tid; i < MAXB * 256;  i += stride) g_pool1u[i] = 0u;
    for (int i = tid; i < MAXB * 1024; i += stride) g_pool2u[i] = 0u;
}

__global__ void k_segid(int N, int B) {
    int n = blockIdx.x * blockDim.x + threadIdx.x;
    if (n >= N) return;
    int s = 0;
    while (s + 1 < B && g_off[s + 1] <= n) s++;
    g_segid[n] = (unsigned char)s;
}

__global__ void k_convW(const float* __restrict__ W2a, const float* __restrict__ W2b,
                        const float* __restrict__ W1b) {
    int i = blockIdx.x * blockDim.x + threadIdx.x;
    if (i < 512 * 512)  g_W2a_h[i] = __float2half_rn(W2a[i]);
    if (i < 1024 * 512) g_W2b_h[i] = __float2half_rn(W2b[i]);
    if (i < 256 * 128)  g_W1b_h[i] = __float2half_rn(W1b[i]);
}

// ---------------- K1a: x moments ----------------
__global__ void k_xstats(const float* __restrict__ x, int N) {
    float s0 = 0, s1 = 0, s2 = 0, q0 = 0, q1 = 0, q2 = 0, q3 = 0, q4 = 0, q5 = 0;
    int stride = gridDim.x * blockDim.x;
    for (int n = blockIdx.x * blockDim.x + threadIdx.x; n < N; n += stride) {
        float a = x[n], b = x[N + n], c = x[2 * N + n];
        s0 += a; s1 += b; s2 += c;
        q0 += a * a; q1 += a * b; q2 += a * c; q3 += b * b; q4 += b * c; q5 += c * c;
    }
    __shared__ float rb[256];
    float vals[9] = {s0, s1, s2, q0, q1, q2, q3, q4, q5};
    for (int v = 0; v < 9; v++) {
        rb[threadIdx.x] = vals[v];
        __syncthreads();
        for (int st = 128; st > 0; st >>= 1) {
            if (threadIdx.x < st) rb[threadIdx.x] += rb[threadIdx.x + st];
            __syncthreads();
        }
        if (threadIdx.x == 0) g_xpart[blockIdx.x * 9 + v] = rb[0];
        __syncthreads();
    }
}

// ---------------- K1b: fold BN1 into conv1a ----------------
__global__ void k_fold1(const float* __restrict__ W1a, const float* __restrict__ b1a,
                        const float* __restrict__ g1,  const float* __restrict__ be1,
                        int N, int nblocks) {
    __shared__ double S[9];
    __shared__ float mu[3], C[3][3];
    if (threadIdx.x < 9) {
        double a = 0;
        for (int b = 0; b < nblocks; b++) a += (double)g_xpart[b * 9 + threadIdx.x];
        S[threadIdx.x] = a;
    }
    __syncthreads();
    if (threadIdx.x == 0) {
        double invN = 1.0 / (double)N;
        double m0 = S[0] * invN, m1 = S[1] * invN, m2 = S[2] * invN;
        mu[0] = (float)m0; mu[1] = (float)m1; mu[2] = (float)m2;
        C[0][0] = (float)(S[3] * invN - m0 * m0);
        C[0][1] = (float)(S[4] * invN - m0 * m1);
        C[0][2] = (float)(S[5] * invN - m0 * m2);
        C[1][1] = (float)(S[6] * invN - m1 * m1);
        C[1][2] = (float)(S[7] * invN - m1 * m2);
        C[2][2] = (float)(S[8] * invN - m2 * m2);
        C[1][0] = C[0][1]; C[2][0] = C[0][2]; C[2][1] = C[1][2];
    }
    __syncthreads();
    int c = threadIdx.x;
    float w0 = W1a[c * 3], w1 = W1a[c * 3 + 1], w2 = W1a[c * 3 + 2];
    float mean1 = w0 * mu[0] + w1 * mu[1] + w2 * mu[2] + b1a[c];
    float var1 = w0 * w0 * C[0][0] + w1 * w1 * C[1][1] + w2 * w2 * C[2][2]
               + 2.f * (w0 * w1 * C[0][1] + w0 * w2 * C[0][2] + w1 * w2 * C[1][2]);
    float a = g1[c] * rsqrtf(var1 + EPSV);
    g_Wf1[c * 3 + 0] = a * w0;
    g_Wf1[c * 3 + 1] = a * w1;
    g_Wf1[c * 3 + 2] = a * w2;
    g_bf1[c] = a * (b1a[c] - mean1) + be1[c];
}

// ---------------- K2: fused front: conv -> mlp(smem) -> GEMM1 -----------------
// 512 threads, 128 points/CTA. Dynamic smem:
//   [0, 69632)        WB: W1b [256][136] fp16, later reused as W2a pipeline
//   [69632, 104448)   Hs: h [128][136] fp16
//   [104448, 174080)  MLP: mlp [256][136] fp16
#define F_SMEM 174080
__global__ void __launch_bounds__(512) k_front(const float* __restrict__ x,
                                               const float* __restrict__ b1b,
                                               const float* __restrict__ b2a,
                                               int N, int B) {
    extern __shared__ __align__(16) char dyn1[];
    const unsigned wbBase  = smem_u32(dyn1);
    const unsigned hsBase  = wbBase + 69632;
    const unsigned mlpBase = wbBase + 104448;
    __half* Hs  = (__half*)(dyn1 + 69632);
    __half* MLP = (__half*)(dyn1 + 104448);
    __shared__ float xs[3][128];
    __shared__ float r0[256][4], r1[256][4], r2[256][4], r3[256][4];
    __shared__ int s_seg, s_bnd;

    const int tid = threadIdx.x, lane = tid & 31, wid = tid >> 5;
    const int wm = wid >> 2, wn = wid & 3;   // 4 c-warps x 4 n-warps (64c x 32n)
    const int quad = lane >> 2, qlane = lane & 3;
    const int n0 = blockIdx.x * 128;

    // W1b -> smem: 256 rows x 128 halves = 4096 cp16 = 8 iters x 512 threads
    #pragma unroll
    for (int i = 0; i < 8; i++) {
        int q = tid + i * 512;
        int r = q >> 4, c8 = (q & 15) * 8;
        cp16(wbBase + ((r * 136 + c8) << 1), g_W1b_h + r * 128 + c8);
    }
    cp_commit();
    if (tid < 384) xs[tid >> 7][tid & 127] = x[(tid >> 7) * N + n0 + (tid & 127)];
    if (tid == 0) {
        int s = g_segid[n0];
        s_seg = s; s_bnd = g_off[s + 1];
    }
    __syncthreads();

    // conv 3->128 (+BN1 fold +ReLU) into Hs
    {
        int c = tid >> 2, p0 = (tid & 3) * 32;
        float w0 = g_Wf1[c * 3], w1 = g_Wf1[c * 3 + 1], w2 = g_Wf1[c * 3 + 2];
        float b = g_bf1[c];
        #pragma unroll
        for (int j = 0; j < 32; j += 2) {
            int p = p0 + j;
            float h0 = fmaxf(b + w0 * xs[0][p]   + w1 * xs[1][p]   + w2 * xs[2][p],   0.f);
            float h1 = fmaxf(b + w0 * xs[0][p+1] + w1 * xs[1][p+1] + w2 * xs[2][p+1], 0.f);
            *(__half2*)&Hs[c * 136 + p] = __floats2half2_rn(h0, h1);
        }
    }
    cp_wait0();
    __syncthreads();

    const int bnd = s_bnd;
    const bool hasB = (bnd < n0 + 128);

    // ---- phase B: mlp = W1b @ h (256x128x128) ----
    {
        float acc[4][4][4];
        #pragma unroll
        for (int m = 0; m < 4; m++)
            #pragma unroll
            for (int n = 0; n < 4; n++)
                #pragma unroll
                for (int v = 0; v < 4; v++) acc[m][n][v] = 0.f;

        unsigned aA0[4], bA0[2];
        #pragma unroll
        for (int mf = 0; mf < 4; mf++)
            aA0[mf] = wbBase + (((wm * 64 + mf * 16 + (lane & 15)) * 136
                                 + (lane >> 4) * 8) << 1);
        #pragma unroll
        for (int np = 0; np < 2; np++)
            bA0[np] = hsBase + (((lane & 15) * 136 + wn * 32 + np * 16
                                 + (lane >> 4) * 8) << 1);

        #pragma unroll
        for (int ks = 0; ks < 8; ks++) {
            unsigned af[4][4], bf[2][4];
            #pragma unroll
            for (int mf = 0; mf < 4; mf++) ldsm_x4(af[mf], aA0[mf] + ks * 32);
            #pragma unroll
            for (int np = 0; np < 2; np++) ldsm_x4_t(bf[np], bA0[np] + ks * 4352);
            #pragma unroll
            for (int mf = 0; mf < 4; mf++)
                #pragma unroll
                for (int nf = 0; nf < 4; nf++)
                    mma16816(acc[mf][nf], af[mf], bf[nf >> 1][(nf & 1) * 2],
                             bf[nf >> 1][(nf & 1) * 2 + 1]);
        }

        // epilogue: bias, write mlp smem, pool1 seg-max
        #pragma unroll
        for (int mf = 0; mf < 4; mf++) {
            int cA = wm * 64 + mf * 16 + quad, cB = cA + 8;
            float bA = b1b[cA], bB = b1b[cB];
            float a0 = -CUDART_INF_F, b0 = -CUDART_INF_F;
            float a1 = -CUDART_INF_F, b1 = -CUDART_INF_F;
            #pragma unroll
            for (int nf = 0; nf < 4; nf++) {
                int nl = wn * 32 + nf * 8 + qlane * 2;
                int n = n0 + nl;
                float v0 = acc[mf][nf][0] + bA;
                float v1 = acc[mf][nf][1] + bA;
                float v2 = acc[mf][nf][2] + bB;
                float v3 = acc[mf][nf][3] + bB;
                *(__half2*)&MLP[cA * 136 + nl] = __floats2half2_rn(v0, v1);
                *(__half2*)&MLP[cB * 136 + nl] = __floats2half2_rn(v2, v3);
                if (n < bnd)     a0 = fmaxf(a0, v0); else b0 = fmaxf(b0, v0);
                if (n + 1 < bnd) a0 = fmaxf(a0, v1); else b0 = fmaxf(b0, v1);
                if (n < bnd)     a1 = fmaxf(a1, v2); else b1 = fmaxf(b1, v2);
                if (n + 1 < bnd) a1 = fmaxf(a1, v3); else b1 = fmaxf(b1, v3);
            }
            a0 = fmaxf(a0, __shfl_xor_sync(0xffffffff, a0, 1));
            a0 = fmaxf(a0, __shfl_xor_sync(0xffffffff, a0, 2));
            a1 = fmaxf(a1, __shfl_xor_sync(0xffffffff, a1, 1));
            a1 = fmaxf(a1, __shfl_xor_sync(0xffffffff, a1, 2));
            b0 = fmaxf(b0, __shfl_xor_sync(0xffffffff, b0, 1));
            b0 = fmaxf(b0, __shfl_xor_sync(0xffffffff, b0, 2));
            b1 = fmaxf(b1, __shfl_xor_sync(0xffffffff, b1, 1));
            b1 = fmaxf(b1, __shfl_xor_sync(0xffffffff, b1, 2));
            if (qlane == 0) {
                r0[cA][wn] = a0; r0[cB][wn] = a1;
                r1[cA][wn] = b0; r1[cB][wn] = b1;
            }
        }
        __syncthreads();
        if (tid < 256) {
            float m = fmaxf(fmaxf(r0[tid][0], r0[tid][1]),
                            fmaxf(r0[tid][2], r0[tid][3]));
            atomicMax(&g_pool1u[s_seg * 256 + tid], fkey(m));
            if (hasB) {
                float mb = fmaxf(fmaxf(r1[tid][0], r1[tid][1]),
                                 fmaxf(r1[tid][2], r1[tid][3]));
                atomicMax(&g_pool1u[(s_seg + 1) * 256 + tid], fkey(mb));
            }
        }
        __syncthreads();
    }

    // ---- phase C: y2p = W2a[:, :256] @ mlp; 2 chunks of 256 channels ----
    const unsigned aOffW = (((wm * 64 + (lane & 15)) * 24 + (lane >> 4) * 8) << 1);
    unsigned bC0[2];
    #pragma unroll
    for (int np = 0; np < 2; np++)
        bC0[np] = mlpBase + (((lane & 15) * 136 + wn * 32 + np * 16
                              + (lane >> 4) * 8) << 1);
    const int nb = blockIdx.x;

    for (int ch = 0; ch < 2; ch++) {
        const int c0 = ch * 256;
        auto issueA = [&](int ks, int s) {
            int row = tid >> 1, c8 = (tid & 1) * 8;
            cp16(wbBase + s * 12288 + ((row * 24 + c8) << 1),
                 g_W2a_h + (size_t)(c0 + row) * 512 + ks * 16 + c8);
        };
        issueA(0, 0); cp_commit();
        issueA(1, 1); cp_commit();
        issueA(2, 2); cp_commit();

        float acc[4][4][4];
        #pragma unroll
        for (int m = 0; m < 4; m++)
            #pragma unroll
            for (int n = 0; n < 4; n++)
                #pragma unroll
                for (int v = 0; v < 4; v++) acc[m][n][v] = 0.f;

        for (int ks = 0; ks < 16; ks++) {
            cp_wait2();
            __syncthreads();
            if (ks + 3 < 16) issueA(ks + 3, (ks + 3) & 3);
            cp_commit();
            unsigned aS = wbBase + (ks & 3) * 12288 + aOffW;
            unsigned af[4][4], bf[2][4];
            #pragma unroll
            for (int mf = 0; mf < 4; mf++) ldsm_x4(af[mf], aS + mf * 768);
            #pragma unroll
            for (int np = 0; np < 2; np++) ldsm_x4_t(bf[np], bC0[np] + ks * 4352);
            #pragma unroll
            for (int mf = 0; mf < 4; mf++)
                #pragma unroll
                for (int nf = 0; nf < 4; nf++)
                    mma16816(acc[mf][nf], af[mf], bf[nf >> 1][(nf & 1) * 2],
                             bf[nf >> 1][(nf & 1) * 2 + 1]);
        }
        __syncthreads();

        // epilogue: write y2p, per-(c, block, seg-half) stat partials
        #pragma unroll
        for (int mf = 0; mf < 4; mf++) {
            int cA = c0 + wm * 64 + mf * 16 + quad, cB = cA + 8;
            float bA = b2a[cA], bB = b2a[cB];
            float s0A = 0, q0A = 0, s1A = 0, q1A = 0;
            float s0B = 0, q0B = 0, s1B = 0, q1B = 0;
            #pragma unroll
            for (int nf = 0; nf < 4; nf++) {
                int n = n0 + wn * 32 + nf * 8 + qlane * 2;
                float v0 = acc[mf][nf][0] + bA;
                float v1 = acc[mf][nf][1] + bA;
                float v2 = acc[mf][nf][2] + bB;
                float v3 = acc[mf][nf][3] + bB;
                *(__half2*)&g_y2h[(size_t)cA * N + n] = __floats2half2_rn(v0, v1);
                *(__half2*)&g_y2h[(size_t)cB * N + n] = __floats2half2_rn(v2, v3);
                if (n < bnd)     { s0A += v0; q0A += v0 * v0; } else { s1A += v0; q1A += v0 * v0; }
                if (n + 1 < bnd) { s0A += v1; q0A += v1 * v1; } else { s1A += v1; q1A += v1 * v1; }
                if (n < bnd)     { s0B += v2; q0B += v2 * v2; } else { s1B += v2; q1B += v2 * v2; }
                if (n + 1 < bnd) { s0B += v3; q0B += v3 * v3; } else { s1B += v3; q1B += v3 * v3; }
            }
            #define RED2(v) v += __shfl_xor_sync(0xffffffff, v, 1); \
                            v += __shfl_xor_sync(0xffffffff, v, 2);
            RED2(s0A) RED2(q0A) RED2(s1A) RED2(q1A)
            RED2(s0B) RED2(q0B) RED2(s1B) RED2(q1B)
            #undef RED2
            if (qlane == 0) {
                int rA = wm * 64 + mf * 16 + quad, rB = rA + 8;
                r0[rA][wn] = s0A; r1[rA][wn] = q0A; r2[rA][wn] = s1A; r3[rA][wn] = q1A;
                r0[rB][wn] = s0B; r1[rB][wn] = q0B; r2[rB][wn] = s1B; r3[rB][wn] = q1B;
            }
        }
        __syncthreads();
        if (tid < 256) {
            float s0 = r0[tid][0] + r0[tid][1] + r0[tid][2] + r0[tid][3];
            float q0 = r1[tid][0] + r1[tid][1] + r1[tid][2] + r1[tid][3];
            float s1 = r2[tid][0] + r2[tid][1] + r2[tid][2] + r2[tid][3];
            float q1 = r3[tid][0] + r3[tid][1] + r3[tid][2] + r3[tid][3];
            size_t base = (size_t)(c0 + tid) * 2048 + nb * 2;
            g_psum[base]     = s0; g_psq[base]     = q0;
            g_psum[base + 1] = s1; g_psq[base + 1] = q1;
        }
        __syncthreads();
    }
}

__global__ void k_decode1(int B) {
    int i = blockIdx.x * blockDim.x + threadIdx.x;
    if (i < B * 256) g_pool1f[i] = funkey(g_pool1u[i]);
}

// ---------------- sym fold: ysym[s][c] = W2a[c][256:512] . pool1[s] (fp32) ----
__global__ void k_symfold(const float* __restrict__ W2a, int B) {
    int c = blockIdx.x;
    int tid = threadIdx.x;
    int s = tid >> 3, kg = tid & 7;
    float acc = 0.f;
    if (s < B) {
        const float* w = W2a + (size_t)c * 512 + 256 + kg * 32;
        const float* p = g_pool1f + s * 256 + kg * 32;
        #pragma unroll
        for (int j = 0; j < 32; j++) acc += w[j] * p[j];
    }
    acc += __shfl_xor_sync(0xffffffff, acc, 1);
    acc += __shfl_xor_sync(0xffffffff, acc, 2);
    acc += __shfl_xor_sync(0xffffffff, acc, 4);
    if (kg == 0 && s < B) g_ysym[s * 512 + c] = acc;
}

// ---------------- BN2 stats with analytic ysym correction --------------------
// y_n = p_n + Y_{seg(n)};  E[y] and E[y^2] from per-(block,half) partials of p.
__global__ void k_bn2(const float* __restrict__ g2, const float* __restrict__ be2,
                      int N, int NB, int B) {
    int c = blockIdx.x;
    int tid = threadIdx.x;
    double t1 = 0, t2 = 0, t3 = 0;
    for (int nb = tid; nb < NB; nb += 256) {
        int sA = g_segid[nb * 128];
        int sB = (sA + 1 < B) ? sA + 1 : B - 1;
        size_t base = (size_t)c * 2048 + nb * 2;
        float sa = g_psum[base], qa = g_psq[base];
        float sb = g_psum[base + 1], qb = g_psq[base + 1];
        t1 += (double)sa + (double)sb;
        t2 += (double)qa + (double)qb;
        t3 += (double)g_ysym[sA * 512 + c] * sa + (double)g_ysym[sB * 512 + c] * sb;
    }
    __shared__ double rs[256], rq[256], rc[256];
    rs[tid] = t1; rq[tid] = t2; rc[tid] = t3;
    __syncthreads();
    for (int st = 128; st > 0; st >>= 1) {
        if (tid < st) { rs[tid] += rs[tid + st]; rq[tid] += rq[tid + st]; rc[tid] += rc[tid + st]; }
        __syncthreads();
    }
    if (tid == 0) {
        double nsY = 0, nsY2 = 0;
        for (int s = 0; s < B; s++) {
            double ns = (double)(g_off[s + 1] - g_off[s]);
            double Y  = (double)g_ysym[s * 512 + c];
            nsY += ns * Y; nsY2 += ns * Y * Y;
        }
        double mean = (rs[0] + nsY) / (double)N;
        double e2   = (rq[0] + 2.0 * rc[0] + nsY2) / (double)N;
        double var  = e2 - mean * mean;
        float a = g2[c] * rsqrtf((float)var + EPSV);
        g_a2[c] = a;
        g_c2[c] = be2[c] - (float)mean * a;
    }
}

// ---------------- GEMM2: activation-resident, 512 threads --------------------
// CTA = 128 points; resident z = relu(a2*(y2p + ysym[seg]) + c2) [512k][136];
// 4 chunks of 256 output channels; fused segment-max epilogue.
#define BIG_SMEM (512 * 136 * 2 + 4 * 12288)
__global__ void __launch_bounds__(512) k_big1(const float* __restrict__ bias,
                                              int N, int B) {
    extern __shared__ __align__(16) char dynm[];
    __half* bres = (__half*)dynm;
    const unsigned bBase = smem_u32(bres);
    const unsigned aBase0 = bBase + 512 * 136 * 2;
    __shared__ float r0[256][4], r1[256][4];
    __shared__ int s_seg, s_bnd;

    const int tid = threadIdx.x, lane = tid & 31, wid = tid >> 5;
    const int wm = wid >> 2, wn = wid & 3;
    const int quad = lane >> 2, qlane = lane & 3;
    const int n0 = blockIdx.x * 128;

    if (tid == 0) {
        int s = g_segid[n0];
        s_seg = s; s_bnd = g_off[s + 1];
    }

    // resident preload of y2p: 512 rows x 128 halves (8192 cp16, 16/thread)
    #pragma unroll
    for (int i = 0; i < 16; i++) {
        int q = tid + i * 512;
        int row = q >> 4, c8 = (q & 15) * 8;
        cp16(bBase + ((row * 136 + c8) << 1), g_y2h + (size_t)row * N + n0 + c8);
    }
    cp_commit(); cp_wait0(); __syncthreads();

    const int bnd = s_bnd;
    const bool hasB = (bnd < n0 + 128);
    const int bl = min(max(bnd - n0, 0), 128);
    {   // in-smem: z = relu(a2*(y2p + ysym[seg(n)]) + c2), row = tid (512 rows)
        int row = tid;
        float a = g_a2[row], cc = g_c2[row];
        int sB2 = (s_seg + 1 < B) ? s_seg + 1 : B - 1;
        float ya = g_ysym[s_seg * 512 + row], yb = g_ysym[sB2 * 512 + row];
        __half2* rp = (__half2*)&bres[row * 136];
        #pragma unroll
        for (int j = 0; j < 64; j++) {
            float2 f = __half22float2(rp[j]);
            float y0 = (2 * j     < bl) ? ya : yb;
            float y1 = (2 * j + 1 < bl) ? ya : yb;
            rp[j] = __floats2half2_rn(fmaxf(fmaf(a, f.x + y0, cc), 0.f),
                                      fmaxf(fmaf(a, f.y + y1, cc), 0.f));
        }
    }
    __syncthreads();

    const unsigned aOffW = (((wm * 64 + (lane & 15)) * 24 + (lane >> 4) * 8) << 1);
    unsigned bA0[2];
    #pragma unroll
    for (int np = 0; np < 2; np++)
        bA0[np] = bBase + (((lane & 15) * 136 + wn * 32 + np * 16
                            + (lane >> 4) * 8) << 1);

    for (int ch = 0; ch < 4; ch++) {
        const int c0 = ch * 256;
        auto issueA = [&](int ks, int s) {
            int row = tid >> 1, c8 = (tid & 1) * 8;
            cp16(aBase0 + s * 12288 + ((row * 24 + c8) << 1),
                 g_W2b_h + (size_t)(c0 + row) * 512 + ks * 16 + c8);
        };
        issueA(0, 0); cp_commit();
        issueA(1, 1); cp_commit();
        issueA(2, 2); cp_commit();

        float acc[4][4][4];
        #pragma unroll
        for (int m = 0; m < 4; m++)
            #pragma unroll
            for (int n = 0; n < 4; n++)
                #pragma unroll
                for (int v = 0; v < 4; v++) acc[m][n][v] = 0.f;

        for (int ks = 0; ks < 32; ks++) {
            cp_wait2();
            __syncthreads();
            if (ks + 3 < 32) issueA(ks + 3, (ks + 3) & 3);
            cp_commit();
            unsigned aS = aBase0 + (ks & 3) * 12288 + aOffW;
            unsigned af[4][4], bf[2][4];
            #pragma unroll
            for (int mf = 0; mf < 4; mf++) ldsm_x4(af[mf], aS + mf * 768);
            #pragma unroll
            for (int np = 0; np < 2; np++) ldsm_x4_t(bf[np], bA0[np] + ks * 4352);
            #pragma unroll
            for (int mf = 0; mf < 4; mf++)
                #pragma unroll
                for (int nf = 0; nf < 4; nf++)
                    mma16816(acc[mf][nf], af[mf], bf[nf >> 1][(nf & 1) * 2],
                             bf[nf >> 1][(nf & 1) * 2 + 1]);
        }
        __syncthreads();

        // segment-max epilogue
        #pragma unroll
        for (int mf = 0; mf < 4; mf++) {
            int cA = c0 + wm * 64 + mf * 16 + quad;
            float bA = bias[cA], bB = bias[cA + 8];
            float a0 = -CUDART_INF_F, b0 = -CUDART_INF_F;
            float a1 = -CUDART_INF_F, b1 = -CUDART_INF_F;
            #pragma unroll
            for (int nf = 0; nf < 4; nf++) {
                int n = n0 + wn * 32 + nf * 8 + qlane * 2;
                float v0 = acc[mf][nf][0] + bA;
                float v1 = acc[mf][nf][1] + bA;
                float v2 = acc[mf][nf][2] + bB;
                float v3 = acc[mf][nf][3] + bB;
                if (n < bnd)     a0 = fmaxf(a0, v0); else b0 = fmaxf(b0, v0);
                if (n + 1 < bnd) a0 = fmaxf(a0, v1); else b0 = fmaxf(b0, v1);
                if (n < bnd)     a1 = fmaxf(a1, v2); else b1 = fmaxf(b1, v2);
                if (n + 1 < bnd) a1 = fmaxf(a1, v3); else b1 = fmaxf(b1, v3);
            }
            a0 = fmaxf(a0, __shfl_xor_sync(0xffffffff, a0, 1));
            a0 = fmaxf(a0, __shfl_xor_sync(0xffffffff, a0, 2));
            a1 = fmaxf(a1, __shfl_xor_sync(0xffffffff, a1, 1));
            a1 = fmaxf(a1, __shfl_xor_sync(0xffffffff, a1, 2));
            if (qlane == 0) {
                int rA = wm * 64 + mf * 16 + quad, rB = rA + 8;
                r0[rA][wn] = a0; r0[rB][wn] = a1;
            }
            if (hasB) {
                b0 = fmaxf(b0, __shfl_xor_sync(0xffffffff, b0, 1));
                b0 = fmaxf(b0, __shfl_xor_sync(0xffffffff, b0, 2));
                b1 = fmaxf(b1, __shfl_xor_sync(0xffffffff, b1, 1));
                b1 = fmaxf(b1, __shfl_xor_sync(0xffffffff, b1, 2));
                if (qlane == 0) {
                    int rA = wm * 64 + mf * 16 + quad, rB = rA + 8;
                    r1[rA][wn] = b0; r1[rB][wn] = b1;
                }
            }
        }
        __syncthreads();
        if (tid < 256) {
            float m = fmaxf(fmaxf(r0[tid][0], r0[tid][1]),
                            fmaxf(r0[tid][2], r0[tid][3]));
            atomicMax(&g_pool2u[s_seg * 1024 + c0 + tid], fkey(m));
            if (hasB) {
                float mb = fmaxf(fmaxf(r1[tid][0], r1[tid][1]),
                                 fmaxf(r1[tid][2], r1[tid][3]));
                atomicMax(&g_pool2u[(s_seg + 1) * 1024 + c0 + tid], fkey(mb));
            }
        }
        __syncthreads();
    }
}

// ---------------- K6: decode output ----------------
__global__ void k_out(float* __restrict__ out, int B) {
    int i = blockIdx.x * blockDim.x + threadIdx.x;
    if (i < B * 1024) out[i] = funkey(g_pool2u[i]);
}

// ---------------- launch ----------------
extern "C" void kernel_launch(void* const* d_in, const int* in_sizes, int n_in,
                              void* d_out, int out_size) {
    const float* x   = (const float*)d_in[0];
    const int*   np  = (const int*)  d_in[1];
    const float* W1a = (const float*)d_in[2];
    const float* b1a = (const float*)d_in[3];
    const float* g1  = (const float*)d_in[4];
    const float* be1 = (const float*)d_in[5];
    const float* W1b = (const float*)d_in[6];
    const float* b1b = (const float*)d_in[7];
    const float* W2a = (const float*)d_in[8];
    const float* b2a = (const float*)d_in[9];
    const float* g2  = (const float*)d_in[10];
    const float* be2 = (const float*)d_in[11];
    const float* W2b = (const float*)d_in[12];
    const float* b2b = (const float*)d_in[13];
    int N = in_sizes[0] / 3;
    int B = in_sizes[1];
    if (N > MAXN) N = MAXN;

    cudaFuncSetAttribute(k_front, cudaFuncAttributeMaxDynamicSharedMemorySize, F_SMEM);
    cudaFuncSetAttribute(k_big1, cudaFuncAttributeMaxDynamicSharedMemorySize, BIG_SMEM);

    k_init<<<32, 256>>>(np, B);
    k_segid<<<(N + 255) / 256, 256>>>(N, B);
    k_convW<<<2048, 256>>>(W2a, W2b, W1b);
    k_xstats<<<128, 256>>>(x, N);
    k_fold1<<<1, 128>>>(W1a, b1a, g1, be1, N, 128);
    k_front<<<N / 128, 512, F_SMEM>>>(x, b1b, b2a, N, B);
    k_decode1<<<(B * 256 + 255) / 256, 256>>>(B);
    k_symfold<<<512, 256>>>(W2a, B);
    k_bn2<<<512, 256>>>(g2, be2, N, N / 128, B);
    k_big1<<<N / 128, 512, BIG_SMEM>>>(b2b, N, B);
    k_out<<<(B * 1024 + 255) / 256, 256>>>((float*)d_out, B);
}

// round 16
// speedup vs baseline: 1.1812x; 1.1812x over previous
#include <cuda_runtime.h>
#include <cuda_fp16.h>
#include <math_constants.h>
#include <cstdint>

#define MAXN 131072
#define MAXB 32
#define EPSV 1e-5f

// ---------------- scratch (static device globals; no allocation) ----------------
__device__ __align__(16) __half g_y2h [512 * MAXN];   // y2 partial (no ysym) fp16 [c][N]
__device__ __align__(16) __half g_W2a_h[512 * 512];
__device__ __align__(16) __half g_W2b_h[1024 * 512];
__device__ __align__(16) __half g_W1b_h[256 * 128];
__device__ float    g_psum[512 * 2048];   // per-(c, block, half) partial sums
__device__ float    g_psq [512 * 2048];
__device__ float    g_xpart[128 * 9];
__device__ float    g_Wf1[128 * 3];
__device__ float    g_bf1[128];
__device__ float    g_a2[512];
__device__ float    g_c2[512];
__device__ unsigned g_pool1u[MAXB * 256];
__device__ float    g_pool1f[MAXB * 256];
__device__ float    g_ysym[MAXB * 512];    // [seg][c] fp32 sym contribution
__device__ unsigned g_pool2u[MAXB * 1024];
__device__ int      g_off[MAXB + 1];
__device__ __align__(8) unsigned char g_segid[MAXN];

// monotonic float<->uint key for exact atomic max
__device__ __forceinline__ unsigned fkey(float f) {
    unsigned u = __float_as_uint(f);
    return (u & 0x80000000u) ? ~u : (u | 0x80000000u);
}
__device__ __forceinline__ float funkey(unsigned k) {
    return (k & 0x80000000u) ? __uint_as_float(k & 0x7fffffffu)
                             : __uint_as_float(~k);
}

// ---------------- PTX helpers ----------------
__device__ __forceinline__ unsigned smem_u32(const void* p) {
    return (unsigned)__cvta_generic_to_shared(p);
}
__device__ __forceinline__ void cp16(unsigned dst, const void* src) {
    asm volatile("cp.async.cg.shared.global [%0], [%1], 16;\n" :: "r"(dst), "l"(src));
}
__device__ __forceinline__ void cp_commit() { asm volatile("cp.async.commit_group;\n" ::); }
__device__ __forceinline__ void cp_wait0()  { asm volatile("cp.async.wait_group 0;\n" ::); }
__device__ __forceinline__ void cp_wait2()  { asm volatile("cp.async.wait_group 2;\n" ::); }
__device__ __forceinline__ void bar_grp(int id) {
    asm volatile("bar.sync %0, %1;" :: "r"(id), "r"(128) : "memory");
}
__device__ __forceinline__ void ldsm_x4(unsigned* r, unsigned addr) {
    asm volatile("ldmatrix.sync.aligned.m8n8.x4.shared.b16 {%0,%1,%2,%3},[%4];"
                 : "=r"(r[0]), "=r"(r[1]), "=r"(r[2]), "=r"(r[3]) : "r"(addr));
}
__device__ __forceinline__ void ldsm_x4_t(unsigned* r, unsigned addr) {
    asm volatile("ldmatrix.sync.aligned.m8n8.x4.trans.shared.b16 {%0,%1,%2,%3},[%4];"
                 : "=r"(r[0]), "=r"(r[1]), "=r"(r[2]), "=r"(r[3]) : "r"(addr));
}
__device__ __forceinline__ void mma16816(float* d, const unsigned* a, unsigned b0, unsigned b1) {
    asm volatile("mma.sync.aligned.m16n8k16.row.col.f32.f16.f16.f32 "
                 "{%0,%1,%2,%3},{%4,%5,%6,%7},{%8,%9},{%0,%1,%2,%3};"
                 : "+f"(d[0]), "+f"(d[1]), "+f"(d[2]), "+f"(d[3])
                 : "r"(a[0]), "r"(a[1]), "r"(a[2]), "r"(a[3]), "r"(b0), "r"(b1));
}

// ---------------- K0: offsets + pool init ----------------
__global__ void k_init(const int* npts, int B) {
    int tid = blockIdx.x * blockDim.x + threadIdx.x;
    if (blockIdx.x == 0 && threadIdx.x == 0) {
        int acc = 0; g_off[0] = 0;
        for (int b = 0; b < B; b++) { acc += npts[b]; g_off[b + 1] = acc; }
    }
    int stride = gridDim.x * blockDim.x;
    for (int i = tid; i < MAXB * 256;  i += stride) g_pool1u[i] = 0u;
    for (int i = tid; i < MAXB * 1024; i += stride) g_pool2u[i] = 0u;
}

__global__ void k_segid(int N, int B) {
    int n = blockIdx.x * blockDim.x + threadIdx.x;
    if (n >= N) return;
    int s = 0;
    while (s + 1 < B && g_off[s + 1] <= n) s++;
    g_segid[n] = (unsigned char)s;
}

__global__ void k_convW(const float* __restrict__ W2a, const float* __restrict__ W2b,
                        const float* __restrict__ W1b) {
    int i = blockIdx.x * blockDim.x + threadIdx.x;
    if (i < 512 * 512)  g_W2a_h[i] = __float2half_rn(W2a[i]);
    if (i < 1024 * 512) g_W2b_h[i] = __float2half_rn(W2b[i]);
    if (i < 256 * 128)  g_W1b_h[i] = __float2half_rn(W1b[i]);
}

// ---------------- K1a: x moments ----------------
__global__ void k_xstats(const float* __restrict__ x, int N) {
    float s0 = 0, s1 = 0, s2 = 0, q0 = 0, q1 = 0, q2 = 0, q3 = 0, q4 = 0, q5 = 0;
    int stride = gridDim.x * blockDim.x;
    for (int n = blockIdx.x * blockDim.x + threadIdx.x; n < N; n += stride) {
        float a = x[n], b = x[N + n], c = x[2 * N + n];
        s0 += a; s1 += b; s2 += c;
        q0 += a * a; q1 += a * b; q2 += a * c; q3 += b * b; q4 += b * c; q5 += c * c;
    }
    __shared__ float rb[256];
    float vals[9] = {s0, s1, s2, q0, q1, q2, q3, q4, q5};
    for (int v = 0; v < 9; v++) {
        rb[threadIdx.x] = vals[v];
        __syncthreads();
        for (int st = 128; st > 0; st >>= 1) {
            if (threadIdx.x < st) rb[threadIdx.x] += rb[threadIdx.x + st];
            __syncthreads();
        }
        if (threadIdx.x == 0) g_xpart[blockIdx.x * 9 + v] = rb[0];
        __syncthreads();
    }
}

// ---------------- K1b: fold BN1 into conv1a ----------------
__global__ void k_fold1(const float* __restrict__ W1a, const float* __restrict__ b1a,
                        const float* __restrict__ g1,  const float* __restrict__ be1,
                        int N, int nblocks) {
    __shared__ double S[9];
    __shared__ float mu[3], C[3][3];
    if (threadIdx.x < 9) {
        double a = 0;
        for (int b = 0; b < nblocks; b++) a += (double)g_xpart[b * 9 + threadIdx.x];
        S[threadIdx.x] = a;
    }
    __syncthreads();
    if (threadIdx.x == 0) {
        double invN = 1.0 / (double)N;
        double m0 = S[0] * invN, m1 = S[1] * invN, m2 = S[2] * invN;
        mu[0] = (float)m0; mu[1] = (float)m1; mu[2] = (float)m2;
        C[0][0] = (float)(S[3] * invN - m0 * m0);
        C[0][1] = (float)(S[4] * invN - m0 * m1);
        C[0][2] = (float)(S[5] * invN - m0 * m2);
        C[1][1] = (float)(S[6] * invN - m1 * m1);
        C[1][2] = (float)(S[7] * invN - m1 * m2);
        C[2][2] = (float)(S[8] * invN - m2 * m2);
        C[1][0] = C[0][1]; C[2][0] = C[0][2]; C[2][1] = C[1][2];
    }
    __syncthreads();
    int c = threadIdx.x;
    float w0 = W1a[c * 3], w1 = W1a[c * 3 + 1], w2 = W1a[c * 3 + 2];
    float mean1 = w0 * mu[0] + w1 * mu[1] + w2 * mu[2] + b1a[c];
    float var1 = w0 * w0 * C[0][0] + w1 * w1 * C[1][1] + w2 * w2 * C[2][2]
               + 2.f * (w0 * w1 * C[0][1] + w0 * w2 * C[0][2] + w1 * w2 * C[1][2]);
    float a = g1[c] * rsqrtf(var1 + EPSV);
    g_Wf1[c * 3 + 0] = a * w0;
    g_Wf1[c * 3 + 1] = a * w1;
    g_Wf1[c * 3 + 2] = a * w2;
    g_bf1[c] = a * (b1a[c] - mean1) + be1[c];
}

// ---------------- K2: fused front: conv -> mlp(smem) -> GEMM1 -----------------
// 512 threads = 4 groups of 4 warps; group g owns output-channel slab [g*64, g*64+64)
// of each 256-channel chunk, with a private 4-stage weight ring + named barrier.
#define F_SMEM 174080
__global__ void __launch_bounds__(512) k_front(const float* __restrict__ x,
                                               const float* __restrict__ b1b,
                                               const float* __restrict__ b2a,
                                               int N, int B) {
    extern __shared__ __align__(16) char dyn1[];
    const unsigned wbBase  = smem_u32(dyn1);
    const unsigned hsBase  = wbBase + 69632;
    const unsigned mlpBase = wbBase + 104448;
    __half* Hs  = (__half*)(dyn1 + 69632);
    __half* MLP = (__half*)(dyn1 + 104448);
    __shared__ float xs[3][128];
    __shared__ float r0[256][4], r1[256][4], r2[256][4], r3[256][4];
    __shared__ int s_seg, s_bnd;

    const int tid = threadIdx.x, lane = tid & 31, wid = tid >> 5;
    const int wm = wid >> 2, wn = wid & 3;   // 4 c-groups x 4 n-warps (64c x 32n)
    const int quad = lane >> 2, qlane = lane & 3;
    const int n0 = blockIdx.x * 128;
    const int g = wm, gt = tid & 127;

    // W1b -> smem: 256 rows x 128 halves = 4096 cp16 = 8 iters x 512 threads
    #pragma unroll
    for (int i = 0; i < 8; i++) {
        int q = tid + i * 512;
        int r = q >> 4, c8 = (q & 15) * 8;
        cp16(wbBase + ((r * 136 + c8) << 1), g_W1b_h + r * 128 + c8);
    }
    cp_commit();
    if (tid < 384) xs[tid >> 7][tid & 127] = x[(tid >> 7) * N + n0 + (tid & 127)];
    if (tid == 0) {
        int s = g_segid[n0];
        s_seg = s; s_bnd = g_off[s + 1];
    }
    __syncthreads();

    // conv 3->128 (+BN1 fold +ReLU) into Hs
    {
        int c = tid >> 2, p0 = (tid & 3) * 32;
        float w0 = g_Wf1[c * 3], w1 = g_Wf1[c * 3 + 1], w2 = g_Wf1[c * 3 + 2];
        float b = g_bf1[c];
        #pragma unroll
        for (int j = 0; j < 32; j += 2) {
            int p = p0 + j;
            float h0 = fmaxf(b + w0 * xs[0][p]   + w1 * xs[1][p]   + w2 * xs[2][p],   0.f);
            float h1 = fmaxf(b + w0 * xs[0][p+1] + w1 * xs[1][p+1] + w2 * xs[2][p+1], 0.f);
            *(__half2*)&Hs[c * 136 + p] = __floats2half2_rn(h0, h1);
        }
    }
    cp_wait0();
    __syncthreads();

    const int bnd = s_bnd;
    const bool hasB = (bnd < n0 + 128);

    // ---- phase B: mlp = W1b @ h (256x128x128) ----
    {
        float acc[4][4][4];
        #pragma unroll
        for (int m = 0; m < 4; m++)
            #pragma unroll
            for (int n = 0; n < 4; n++)
                #pragma unroll
                for (int v = 0; v < 4; v++) acc[m][n][v] = 0.f;

        unsigned aA0[4], bA0[2];
        #pragma unroll
        for (int mf = 0; mf < 4; mf++)
            aA0[mf] = wbBase + (((wm * 64 + mf * 16 + (lane & 15)) * 136
                                 + (lane >> 4) * 8) << 1);
        #pragma unroll
        for (int np = 0; np < 2; np++)
            bA0[np] = hsBase + (((lane & 15) * 136 + wn * 32 + np * 16
                                 + (lane >> 4) * 8) << 1);

        #pragma unroll
        for (int ks = 0; ks < 8; ks++) {
            unsigned af[4][4], bf[2][4];
            #pragma unroll
            for (int mf = 0; mf < 4; mf++) ldsm_x4(af[mf], aA0[mf] + ks * 32);
            #pragma unroll
            for (int np = 0; np < 2; np++) ldsm_x4_t(bf[np], bA0[np] + ks * 4352);
            #pragma unroll
            for (int mf = 0; mf < 4; mf++)
                #pragma unroll
                for (int nf = 0; nf < 4; nf++)
                    mma16816(acc[mf][nf], af[mf], bf[nf >> 1][(nf & 1) * 2],
                             bf[nf >> 1][(nf & 1) * 2 + 1]);
        }

        // epilogue: bias, write mlp smem, pool1 seg-max
        #pragma unroll
        for (int mf = 0; mf < 4; mf++) {
            int cA = wm * 64 + mf * 16 + quad, cB = cA + 8;
            float bA = b1b[cA], bB = b1b[cB];
            float a0 = -CUDART_INF_F, b0 = -CUDART_INF_F;
            float a1 = -CUDART_INF_F, b1 = -CUDART_INF_F;
            #pragma unroll
            for (int nf = 0; nf < 4; nf++) {
                int nl = wn * 32 + nf * 8 + qlane * 2;
                int n = n0 + nl;
                float v0 = acc[mf][nf][0] + bA;
                float v1 = acc[mf][nf][1] + bA;
                float v2 = acc[mf][nf][2] + bB;
                float v3 = acc[mf][nf][3] + bB;
                *(__half2*)&MLP[cA * 136 + nl] = __floats2half2_rn(v0, v1);
                *(__half2*)&MLP[cB * 136 + nl] = __floats2half2_rn(v2, v3);
                if (n < bnd)     a0 = fmaxf(a0, v0); else b0 = fmaxf(b0, v0);
                if (n + 1 < bnd) a0 = fmaxf(a0, v1); else b0 = fmaxf(b0, v1);
                if (n < bnd)     a1 = fmaxf(a1, v2); else b1 = fmaxf(b1, v2);
                if (n + 1 < bnd) a1 = fmaxf(a1, v3); else b1 = fmaxf(b1, v3);
            }
            a0 = fmaxf(a0, __shfl_xor_sync(0xffffffff, a0, 1));
            a0 = fmaxf(a0, __shfl_xor_sync(0xffffffff, a0, 2));
            a1 = fmaxf(a1, __shfl_xor_sync(0xffffffff, a1, 1));
            a1 = fmaxf(a1, __shfl_xor_sync(0xffffffff, a1, 2));
            b0 = fmaxf(b0, __shfl_xor_sync(0xffffffff, b0, 1));
            b0 = fmaxf(b0, __shfl_xor_sync(0xffffffff, b0, 2));
            b1 = fmaxf(b1, __shfl_xor_sync(0xffffffff, b1, 1));
            b1 = fmaxf(b1, __shfl_xor_sync(0xffffffff, b1, 2));
            if (qlane == 0) {
                r0[cA][wn] = a0; r0[cB][wn] = a1;
                r1[cA][wn] = b0; r1[cB][wn] = b1;
            }
        }
        __syncthreads();
        if (tid < 256) {
            float m = fmaxf(fmaxf(r0[tid][0], r0[tid][1]),
                            fmaxf(r0[tid][2], r0[tid][3]));
            atomicMax(&g_pool1u[s_seg * 256 + tid], fkey(m));
            if (hasB) {
                float mb = fmaxf(fmaxf(r1[tid][0], r1[tid][1]),
                                 fmaxf(r1[tid][2], r1[tid][3]));
                atomicMax(&g_pool1u[(s_seg + 1) * 256 + tid], fkey(mb));
            }
        }
        __syncthreads();
    }

    // ---- phase C: y2p = W2a[:, :256] @ mlp; unified 32-step group pipeline ----
    // NOTE: cp_commit is UNCONDITIONAL per step (empty groups when no issue) so
    // that wait_group 2 at step k always implies stage k's group completed.
    const unsigned aLane = (((lane & 15) * 24 + (lane >> 4) * 8) << 1);
    const unsigned ringG = wbBase + g * 12288;
    unsigned bC0[2];
    #pragma unroll
    for (int np = 0; np < 2; np++)
        bC0[np] = mlpBase + (((lane & 15) * 136 + wn * 32 + np * 16
                              + (lane >> 4) * 8) << 1);
    const int nb = blockIdx.x;

    auto issueC = [&](int kglob) {   // kglob in [0,32): chunk = kglob>>4, ks = kglob&15
        int row = gt >> 1, c8 = (gt & 1) * 8;
        cp16(ringG + (kglob & 3) * 3072 + ((row * 24 + c8) << 1),
             g_W2a_h + (size_t)(((kglob >> 4) << 8) + g * 64 + row) * 512
                     + (kglob & 15) * 16 + c8);
    };
    issueC(0); cp_commit();
    issueC(1); cp_commit();
    issueC(2); cp_commit();

    for (int ch = 0; ch < 2; ch++) {
        const int c0 = ch * 256;
        float acc[4][4][4];
        #pragma unroll
        for (int m = 0; m < 4; m++)
            #pragma unroll
            for (int n = 0; n < 4; n++)
                #pragma unroll
                for (int v = 0; v < 4; v++) acc[m][n][v] = 0.f;

        for (int ks = 0; ks < 16; ks++) {
            int kglob = ch * 16 + ks;
            cp_wait2();
            bar_grp(1 + g);
            if (kglob + 3 < 32) issueC(kglob + 3);
            cp_commit();
            unsigned aS = ringG + (kglob & 3) * 3072 + aLane;
            unsigned af[4][4], bf[2][4];
            #pragma unroll
            for (int mf = 0; mf < 4; mf++) ldsm_x4(af[mf], aS + mf * 768);
            #pragma unroll
            for (int np = 0; np < 2; np++) ldsm_x4_t(bf[np], bC0[np] + ks * 4352);
            #pragma unroll
            for (int mf = 0; mf < 4; mf++)
                #pragma unroll
                for (int nf = 0; nf < 4; nf++)
                    mma16816(acc[mf][nf], af[mf], bf[nf >> 1][(nf & 1) * 2],
                             bf[nf >> 1][(nf & 1) * 2 + 1]);
        }

        // epilogue: write y2p, per-(c, block, seg-half) stat partials
        #pragma unroll
        for (int mf = 0; mf < 4; mf++) {
            int cA = c0 + wm * 64 + mf * 16 + quad, cB = cA + 8;
            float bA = b2a[cA], bB = b2a[cB];
            float s0A = 0, q0A = 0, s1A = 0, q1A = 0;
            float s0B = 0, q0B = 0, s1B = 0, q1B = 0;
            #pragma unroll
            for (int nf = 0; nf < 4; nf++) {
                int n = n0 + wn * 32 + nf * 8 + qlane * 2;
                float v0 = acc[mf][nf][0] + bA;
                float v1 = acc[mf][nf][1] + bA;
                float v2 = acc[mf][nf][2] + bB;
                float v3 = acc[mf][nf][3] + bB;
                *(__half2*)&g_y2h[(size_t)cA * N + n] = __floats2half2_rn(v0, v1);
                *(__half2*)&g_y2h[(size_t)cB * N + n] = __floats2half2_rn(v2, v3);
                if (n < bnd)     { s0A += v0; q0A += v0 * v0; } else { s1A += v0; q1A += v0 * v0; }
                if (n + 1 < bnd) { s0A += v1; q0A += v1 * v1; } else { s1A += v1; q1A += v1 * v1; }
                if (n < bnd)     { s0B += v2; q0B += v2 * v2; } else { s1B += v2; q1B += v2 * v2; }
                if (n + 1 < bnd) { s0B += v3; q0B += v3 * v3; } else { s1B += v3; q1B += v3 * v3; }
            }
            #define RED2(v) v += __shfl_xor_sync(0xffffffff, v, 1); \
                            v += __shfl_xor_sync(0xffffffff, v, 2);
            RED2(s0A) RED2(q0A) RED2(s1A) RED2(q1A)
            RED2(s0B) RED2(q0B) RED2(s1B) RED2(q1B)
            #undef RED2
            if (qlane == 0) {
                int rA = wm * 64 + mf * 16 + quad, rB = rA + 8;
                r0[rA][wn] = s0A; r1[rA][wn] = q0A; r2[rA][wn] = s1A; r3[rA][wn] = q1A;
                r0[rB][wn] = s0B; r1[rB][wn] = q0B; r2[rB][wn] = s1B; r3[rB][wn] = q1B;
            }
        }
        __syncthreads();
        if (tid < 256) {
            float s0 = r0[tid][0] + r0[tid][1] + r0[tid][2] + r0[tid][3];
            float q0 = r1[tid][0] + r1[tid][1] + r1[tid][2] + r1[tid][3];
            float s1 = r2[tid][0] + r2[tid][1] + r2[tid][2] + r2[tid][3];
            float q1 = r3[tid][0] + r3[tid][1] + r3[tid][2] + r3[tid][3];
            size_t base = (size_t)(c0 + tid) * 2048 + nb * 2;
            g_psum[base]     = s0; g_psq[base]     = q0;
            g_psum[base + 1] = s1; g_psq[base + 1] = q1;
        }
        __syncthreads();
    }
}

__global__ void k_decode1(int B) {
    int i = blockIdx.x * blockDim.x + threadIdx.x;
    if (i < B * 256) g_pool1f[i] = funkey(g_pool1u[i]);
}

// ---------------- sym fold: ysym[s][c] = W2a[c][256:512] . pool1[s] (fp32) ----
__global__ void k_symfold(const float* __restrict__ W2a, int B) {
    int c = blockIdx.x;
    int tid = threadIdx.x;
    int s = tid >> 3, kg = tid & 7;
    float acc = 0.f;
    if (s < B) {
        const float* w = W2a + (size_t)c * 512 + 256 + kg * 32;
        const float* p = g_pool1f + s * 256 + kg * 32;
        #pragma unroll
        for (int j = 0; j < 32; j++) acc += w[j] * p[j];
    }
    acc += __shfl_xor_sync(0xffffffff, acc, 1);
    acc += __shfl_xor_sync(0xffffffff, acc, 2);
    acc += __shfl_xor_sync(0xffffffff, acc, 4);
    if (kg == 0 && s < B) g_ysym[s * 512 + c] = acc;
}

// ---------------- BN2 stats with analytic ysym correction --------------------
__global__ void k_bn2(const float* __restrict__ g2, const float* __restrict__ be2,
                      int N, int NB, int B) {
    int c = blockIdx.x;
    int tid = threadIdx.x;
    double t1 = 0, t2 = 0, t3 = 0;
    for (int nb = tid; nb < NB; nb += 256) {
        int sA = g_segid[nb * 128];
        int sB = (sA + 1 < B) ? sA + 1 : B - 1;
        size_t base = (size_t)c * 2048 + nb * 2;
        float sa = g_psum[base], qa = g_psq[base];
        float sb = g_psum[base + 1], qb = g_psq[base + 1];
        t1 += (double)sa + (double)sb;
        t2 += (double)qa + (double)qb;
        t3 += (double)g_ysym[sA * 512 + c] * sa + (double)g_ysym[sB * 512 + c] * sb;
    }
    __shared__ double rs[256], rq[256], rc[256];
    rs[tid] = t1; rq[tid] = t2; rc[tid] = t3;
    __syncthreads();
    for (int st = 128; st > 0; st >>= 1) {
        if (tid < st) { rs[tid] += rs[tid + st]; rq[tid] += rq[tid + st]; rc[tid] += rc[tid + st]; }
        __syncthreads();
    }
    if (tid == 0) {
        double nsY = 0, nsY2 = 0;
        for (int s = 0; s < B; s++) {
            double ns = (double)(g_off[s + 1] - g_off[s]);
            double Y  = (double)g_ysym[s * 512 + c];
            nsY += ns * Y; nsY2 += ns * Y * Y;
        }
        double mean = (rs[0] + nsY) / (double)N;
        double e2   = (rq[0] + 2.0 * rc[0] + nsY2) / (double)N;
        double var  = e2 - mean * mean;
        float a = g2[c] * rsqrtf((float)var + EPSV);
        g_a2[c] = a;
        g_c2[c] = be2[c] - (float)mean * a;
    }
}

// ---------------- GEMM2: activation-resident, group-pipelined ----------------
// CTA = 128 points; resident z = relu(a2*(y2p + ysym[seg]) + c2) [512k][136];
// unified 128-step pipeline over 4 chunks of 256 output channels; per-group
// private weight rings + named barriers; unconditional per-step commits.
#define BIG_SMEM (512 * 136 * 2 + 4 * 12288)
__global__ void __launch_bounds__(512) k_big1(const float* __restrict__ bias,
                                              int N, int B) {
    extern __shared__ __align__(16) char dynm[];
    __half* bres = (__half*)dynm;
    const unsigned bBase = smem_u32(bres);
    const unsigned aBase0 = bBase + 512 * 136 * 2;
    __shared__ float r0[256][4], r1[256][4];
    __shared__ int s_seg, s_bnd;

    const int tid = threadIdx.x, lane = tid & 31, wid = tid >> 5;
    const int wm = wid >> 2, wn = wid & 3;
    const int quad = lane >> 2, qlane = lane & 3;
    const int n0 = blockIdx.x * 128;
    const int g = wm, gt = tid & 127;

    if (tid == 0) {
        int s = g_segid[n0];
        s_seg = s; s_bnd = g_off[s + 1];
    }

    // resident preload of y2p: 512 rows x 128 halves (8192 cp16, 16/thread)
    #pragma unroll
    for (int i = 0; i < 16; i++) {
        int q = tid + i * 512;
        int row = q >> 4, c8 = (q & 15) * 8;
        cp16(bBase + ((row * 136 + c8) << 1), g_y2h + (size_t)row * N + n0 + c8);
    }
    cp_commit(); cp_wait0(); __syncthreads();

    const int bnd = s_bnd;
    const bool hasB = (bnd < n0 + 128);
    const int bl = min(max(bnd - n0, 0), 128);
    {   // in-smem: z = relu(a2*(y2p + ysym[seg(n)]) + c2), row = tid (512 rows)
        int row = tid;
        float a = g_a2[row], cc = g_c2[row];
        int sB2 = (s_seg + 1 < B) ? s_seg + 1 : B - 1;
        float ya = g_ysym[s_seg * 512 + row], yb = g_ysym[sB2 * 512 + row];
        __half2* rp = (__half2*)&bres[row * 136];
        #pragma unroll
        for (int j = 0; j < 64; j++) {
            float2 f = __half22float2(rp[j]);
            float y0 = (2 * j     < bl) ? ya : yb;
            float y1 = (2 * j + 1 < bl) ? ya : yb;
            rp[j] = __floats2half2_rn(fmaxf(fmaf(a, f.x + y0, cc), 0.f),
                                      fmaxf(fmaf(a, f.y + y1, cc), 0.f));
        }
    }
    __syncthreads();

    const unsigned aLane = (((lane & 15) * 24 + (lane >> 4) * 8) << 1);
    const unsigned ringG = aBase0 + g * 12288;
    unsigned bA0[2];
    #pragma unroll
    for (int np = 0; np < 2; np++)
        bA0[np] = bBase + (((lane & 15) * 136 + wn * 32 + np * 16
                            + (lane >> 4) * 8) << 1);

    auto issueW = [&](int kglob) {  // kglob in [0,128): chunk = kglob>>5, ks = kglob&31
        int row = gt >> 1, c8 = (gt & 1) * 8;
        cp16(ringG + (kglob & 3) * 3072 + ((row * 24 + c8) << 1),
             g_W2b_h + (size_t)(((kglob >> 5) << 8) + g * 64 + row) * 512
                     + (kglob & 31) * 16 + c8);
    };
    issueW(0); cp_commit();
    issueW(1); cp_commit();
    issueW(2); cp_commit();

    for (int ch = 0; ch < 4; ch++) {
        const int c0 = ch * 256;
        float acc[4][4][4];
        #pragma unroll
        for (int m = 0; m < 4; m++)
            #pragma unroll
            for (int n = 0; n < 4; n++)
                #pragma unroll
                for (int v = 0; v < 4; v++) acc[m][n][v] = 0.f;

        for (int ks = 0; ks < 32; ks++) {
            int kglob = ch * 32 + ks;
            cp_wait2();
            bar_grp(1 + g);
            if (kglob + 3 < 128) issueW(kglob + 3);
            cp_commit();
            unsigned aS = ringG + (kglob & 3) * 3072 + aLane;
            unsigned af[4][4], bf[2][4];
            #pragma unroll
            for (int mf = 0; mf < 4; mf++) ldsm_x4(af[mf], aS + mf * 768);
            #pragma unroll
            for (int np = 0; np < 2; np++) ldsm_x4_t(bf[np], bA0[np] + ks * 4352);
            #pragma unroll
            for (int mf = 0; mf < 4; mf++)
                #pragma unroll
                for (int nf = 0; nf < 4; nf++)
                    mma16816(acc[mf][nf], af[mf], bf[nf >> 1][(nf & 1) * 2],
                             bf[nf >> 1][(nf & 1) * 2 + 1]);
        }

        // segment-max epilogue (pipeline for next chunk already in flight)
        #pragma unroll
        for (int mf = 0; mf < 4; mf++) {
            int cA = c0 + wm * 64 + mf * 16 + quad;
            float bA = bias[cA], bB = bias[cA + 8];
            float a0 = -CUDART_INF_F, b0 = -CUDART_INF_F;
            float a1 = -CUDART_INF_F, b1 = -CUDART_INF_F;
            #pragma unroll
            for (int nf = 0; nf < 4; nf++) {
                int n = n0 + wn * 32 + nf * 8 + qlane * 2;
                float v0 = acc[mf][nf][0] + bA;
                float v1 = acc[mf][nf][1] + bA;
                float v2 = acc[mf][nf][2] + bB;
                float v3 = acc[mf][nf][3] + bB;
                if (n < bnd)     a0 = fmaxf(a0, v0); else b0 = fmaxf(b0, v0);
                if (n + 1 < bnd) a0 = fmaxf(a0, v1); else b0 = fmaxf(b0, v1);
                if (n < bnd)     a1 = fmaxf(a1, v2); else b1 = fmaxf(b1, v2);
                if (n + 1 < bnd) a1 = fmaxf(a1, v3); else b1 = fmaxf(b1, v3);
            }
            a0 = fmaxf(a0, __shfl_xor_sync(0xffffffff, a0, 1));
            a0 = fmaxf(a0, __shfl_xor_sync(0xffffffff, a0, 2));
            a1 = fmaxf(a1, __shfl_xor_sync(0xffffffff, a1, 1));
            a1 = fmaxf(a1, __shfl_xor_sync(0xffffffff, a1, 2));
            if (qlane == 0) {
                int rA = wm * 64 + mf * 16 + quad, rB = rA + 8;
                r0[rA][wn] = a0; r0[rB][wn] = a1;
            }
            if (hasB) {
                b0 = fmaxf(b0, __shfl_xor_sync(0xffffffff, b0, 1));
                b0 = fmaxf(b0, __shfl_xor_sync(0xffffffff, b0, 2));
                b1 = fmaxf(b1, __shfl_xor_sync(0xffffffff, b1, 1));
                b1 = fmaxf(b1, __shfl_xor_sync(0xffffffff, b1, 2));
                if (qlane == 0) {
                    int rA = wm * 64 + mf * 16 + quad, rB = rA + 8;
                    r1[rA][wn] = b0; r1[rB][wn] = b1;
                }
            }
        }
        __syncthreads();
        if (tid < 256) {
            float m = fmaxf(fmaxf(r0[tid][0], r0[tid][1]),
                            fmaxf(r0[tid][2], r0[tid][3]));
            atomicMax(&g_pool2u[s_seg * 1024 + c0 + tid], fkey(m));
            if (hasB) {
                float mb = fmaxf(fmaxf(r1[tid][0], r1[tid][1]),
                                 fmaxf(r1[tid][2], r1[tid][3]));
                atomicMax(&g_pool2u[(s_seg + 1) * 1024 + c0 + tid], fkey(mb));
            }
        }
        __syncthreads();
    }
}

// ---------------- K6: decode output ----------------
__global__ void k_out(float* __restrict__ out, int B) {
    int i = blockIdx.x * blockDim.x + threadIdx.x;
    if (i < B * 1024) out[i] = funkey(g_pool2u[i]);
}

// ---------------- launch ----------------
extern "C" void kernel_launch(void* const* d_in, const int* in_sizes, int n_in,
                              void* d_out, int out_size) {
    const float* x   = (const float*)d_in[0];
    const int*   np  = (const int*)  d_in[1];
    const float* W1a = (const float*)d_in[2];
    const float* b1a = (const float*)d_in[3];
    const float* g1  = (const float*)d_in[4];
    const float* be1 = (const float*)d_in[5];
    const float* W1b = (const float*)d_in[6];
    const float* b1b = (const float*)d_in[7];
    const float* W2a = (const float*)d_in[8];
    const float* b2a = (const float*)d_in[9];
    const float* g2  = (const float*)d_in[10];
    const float* be2 = (const float*)d_in[11];
    const float* W2b = (const float*)d_in[12];
    const float* b2b = (const float*)d_in[13];
    int N = in_sizes[0] / 3;
    int B = in_sizes[1];
    if (N > MAXN) N = MAXN;

    cudaFuncSetAttribute(k_front, cudaFuncAttributeMaxDynamicSharedMemorySize, F_SMEM);
    cudaFuncSetAttribute(k_big1, cudaFuncAttributeMaxDynamicSharedMemorySize, BIG_SMEM);

    k_init<<<32, 256>>>(np, B);
    k_segid<<<(N + 255) / 256, 256>>>(N, B);
    k_convW<<<2048, 256>>>(W2a, W2b, W1b);
    k_xstats<<<128, 256>>>(x, N);
    k_fold1<<<1, 128>>>(W1a, b1a, g1, be1, N, 128);
    k_front<<<N / 128, 512, F_SMEM>>>(x, b1b, b2a, N, B);
    k_decode1<<<(B * 256 + 255) / 256, 256>>>(B);
    k_symfold<<<512, 256>>>(W2a, B);
    k_bn2<<<512, 256>>>(g2, be2, N, N / 128, B);
    k_big1<<<N / 128, 512, BIG_SMEM>>>(b2b, N, B);
    k_out<<<(B * 1024 + 255) / 256, 256>>>((float*)d_out, B);
}